// round 1
// baseline (speedup 1.0000x reference)
#include <cuda_runtime.h>
#include <math.h>

namespace {

constexpr int kB    = 4;      // basis kernels
constexpr int kH    = 8;      // heads
constexpr int kHPT  = 4;      // heads per thread (grid.y = kH/kHPT)
constexpr int kNI   = 16384;  // BATCH * N
constexpr int kBlk  = 128;

__device__ int g_dt_default = 1;

__device__ __forceinline__ unsigned long long pack2(float lo, float hi) {
    unsigned long long r;
    asm("mov.b64 %0, {%1, %2};" : "=l"(r) : "f"(lo), "f"(hi));
    return r;
}
__device__ __forceinline__ void unpack2(unsigned long long v, float& lo, float& hi) {
    asm("mov.b64 {%0, %1}, %2;" : "=f"(lo), "=f"(hi) : "l"(v));
}
__device__ __forceinline__ unsigned long long fma2(unsigned long long a,
                                                   unsigned long long b,
                                                   unsigned long long c) {
    unsigned long long r;
    asm("fma.rn.f32x2 %0, %1, %2, %3;" : "=l"(r) : "l"(a), "l"(b), "l"(c));
    return r;
}
__device__ __forceinline__ unsigned long long mul2(unsigned long long a,
                                                   unsigned long long b) {
    unsigned long long r;
    asm("mul.rn.f32x2 %0, %1, %2;" : "=l"(r) : "l"(a), "l"(b));
    return r;
}

// dt arrives as a scalar; reference passes python int 1. Handle either an
// int32 or a float32 payload robustly (deterministic for fixed input).
__device__ __forceinline__ float resolve_dt(const int* dt_raw) {
    int v = __ldg(dt_raw);
    float f = __int_as_float(v);
    float af = fabsf(f);
    if (af >= 1e-6f && af <= 1e6f) return f;   // bits look like a sane float
    return (float)v;                            // else it was an integer
}

// ---------------------------------------------------------------------------
// Fast kernel: fixed shapes (B=4, H=8, NI=16384). Each thread owns one
// (batch,n) column and 4 heads. grid = (NI/128, 2).
// ---------------------------------------------------------------------------
__global__ void __launch_bounds__(kBlk)
tb_fast(const float* __restrict__ z0, const float* __restrict__ spikes,
        const float* __restrict__ taus, const float* __restrict__ coeffs,
        const int* __restrict__ dt_raw, float* __restrict__ out, int T)
{
    const int idx   = blockIdx.x * kBlk + threadIdx.x;
    const int hbase = blockIdx.y * kHPT;

    const float dt = resolve_dt(dt_raw);

    float d[kB];
#pragma unroll
    for (int k = 0; k < kB; ++k)
        d[k] = (float)exp(-(double)dt / (double)__ldg(&taus[k]));

    float c[kHPT][kB];
#pragma unroll
    for (int h = 0; h < kHPT; ++h)
#pragma unroll
        for (int k = 0; k < kB; ++k)
            c[h][k] = __ldg(&coeffs[(hbase + h) * kB + k]);

    // This thread's initial states (z0 layout: [H, NI, B], 16B aligned)
    float4 zi[kHPT];
    bool allz = true;
#pragma unroll
    for (int h = 0; h < kHPT; ++h) {
        zi[h] = *reinterpret_cast<const float4*>(
            z0 + ((size_t)(hbase + h) * kNI + idx) * kB);
        allz = allz && (zi[h].x == 0.0f) && (zi[h].y == 0.0f) &&
                       (zi[h].z == 0.0f) && (zi[h].w == 0.0f);
    }

    const float* sp = spikes + idx;
    float* op = out + (size_t)hbase * kNI + idx;
    const long long OSTEP = (long long)kH * kNI;

    if (allz) {
        // z identical across heads: carry 4 shared states, packed as f32x2.
        const unsigned long long d01 = pack2(d[0], d[1]);
        const unsigned long long d23 = pack2(d[2], d[3]);
        unsigned long long cw01[kHPT], cw23[kHPT];
#pragma unroll
        for (int h = 0; h < kHPT; ++h) {
            cw01[h] = pack2(c[h][0], c[h][1]);
            cw23[h] = pack2(c[h][2], c[h][3]);
        }
        unsigned long long w01 = 0ull, w23 = 0ull;  // (0.f, 0.f)

        constexpr int PF = 8;
        float sA[PF];
#pragma unroll
        for (int j = 0; j < PF; ++j) sA[j] = __ldg(sp + (size_t)j * kNI);
        sp += (size_t)PF * kNI;

        for (int t0 = 0; t0 < T; t0 += PF) {
            float sB[PF];
            if (t0 + PF < T) {
#pragma unroll
                for (int j = 0; j < PF; ++j) sB[j] = __ldg(sp + (size_t)j * kNI);
            } else {
#pragma unroll
                for (int j = 0; j < PF; ++j) sB[j] = 0.0f;
            }
            sp += (size_t)PF * kNI;

#pragma unroll
            for (int j = 0; j < PF; ++j) {
                const unsigned long long ss = pack2(sA[j], sA[j]);
                w01 = fma2(d01, w01, ss);
                w23 = fma2(d23, w23, ss);
#pragma unroll
                for (int h = 0; h < kHPT; ++h) {
                    unsigned long long p = fma2(cw23[h], w23, mul2(cw01[h], w01));
                    float lo, hi;
                    unpack2(p, lo, hi);
                    __stcs(op + (size_t)h * kNI, lo + hi);
                }
                op += OSTEP;
            }
#pragma unroll
            for (int j = 0; j < PF; ++j) sA[j] = sB[j];
        }
    } else {
        // General z0 path (not exercised by this dataset, kept for correctness)
        float zz[kHPT][kB];
#pragma unroll
        for (int h = 0; h < kHPT; ++h) {
            zz[h][0] = zi[h].x; zz[h][1] = zi[h].y;
            zz[h][2] = zi[h].z; zz[h][3] = zi[h].w;
        }
        for (int t = 0; t < T; ++t) {
            const float s = __ldg(sp);
            sp += kNI;
#pragma unroll
            for (int h = 0; h < kHPT; ++h) {
                float r = 0.0f;
#pragma unroll
                for (int k = 0; k < kB; ++k) {
                    zz[h][k] = fmaf(d[k], zz[h][k], s);
                    r = fmaf(c[h][k], zz[h][k], r);
                }
                __stcs(op + (size_t)h * kNI, r);
            }
            op += OSTEP;
        }
    }
}

// ---------------------------------------------------------------------------
// Generic fallback (any shapes, Bn <= 16): one thread per (head, idx).
// ---------------------------------------------------------------------------
__global__ void tb_generic(const float* __restrict__ z0,
                           const float* __restrict__ spikes,
                           const float* __restrict__ taus,
                           const float* __restrict__ coeffs,
                           const int* __restrict__ dt_raw,
                           float* __restrict__ out,
                           int T, int NI, int Hn, int Bn)
{
    const int gid = blockIdx.x * blockDim.x + threadIdx.x;
    if (gid >= NI * Hn) return;
    const int idx = gid % NI;
    const int h   = gid / NI;

    const float dt = resolve_dt(dt_raw);

    constexpr int BMAX = 16;
    float z[BMAX], dk[BMAX], ck[BMAX];
    const int Bc = Bn < BMAX ? Bn : BMAX;
    for (int k = 0; k < Bc; ++k) {
        dk[k] = (float)exp(-(double)dt / (double)taus[k]);
        ck[k] = coeffs[h * Bn + k];
        z[k]  = z0[((size_t)h * NI + idx) * Bn + k];
    }
    const float* sp = spikes + idx;
    float* op = out + (size_t)h * NI + idx;
    for (int t = 0; t < T; ++t) {
        const float s = sp[(size_t)t * NI];
        float r = 0.0f;
        for (int k = 0; k < Bc; ++k) {
            z[k] = fmaf(dk[k], z[k], s);
            r = fmaf(ck[k], z[k], r);
        }
        op[(size_t)t * Hn * NI] = r;
    }
}

}  // namespace

extern "C" void kernel_launch(void* const* d_in, const int* in_sizes, int n_in,
                              void* d_out, int out_size)
{
    const float* z0     = (const float*)d_in[0];
    const float* spikes = (const float*)d_in[1];
    const float* taus   = (const float*)d_in[2];
    const float* coeffs = (const float*)d_in[3];

    const int* dt_ptr;
    if (n_in >= 5) {
        dt_ptr = (const int*)d_in[4];
    } else {
        static int* p = nullptr;
        if (!p) cudaGetSymbolAddress((void**)&p, g_dt_default);
        dt_ptr = p;
    }

    float* out = (float*)d_out;

    const int Bn = in_sizes[2];
    const int Hn = in_sizes[3] / Bn;
    const int NI = in_sizes[0] / (Hn * Bn);
    const int T  = in_sizes[1] / NI;

    if (Bn == kB && Hn == kH && NI == kNI && (T % 8) == 0) {
        dim3 grid(kNI / kBlk, kH / kHPT);
        tb_fast<<<grid, kBlk>>>(z0, spikes, taus, coeffs, dt_ptr, out, T);
    } else {
        const int threads = NI * Hn;
        tb_generic<<<(threads + 127) / 128, 128>>>(
            z0, spikes, taus, coeffs, dt_ptr, out, T, NI, Hn, Bn);
    }
}